// round 10
// baseline (speedup 1.0000x reference)
#include <cuda_runtime.h>

// ---------------- problem constants ----------------
#define NA 3
#define GH 52
#define GW 52
#define NCLS 80
#define PLANE (GH*GW)             // 2704
#define NBMW ((PLANE + 31) / 32)  // 85 bitmap words
#define EPSF 1e-7f
#define LOG1MEPS 1.00000011686097e-07f   // -log(1 - 1e-7)
#define XCLIP 16.118095f          // log((1-EPS)/EPS)
#define TPB 1024
#define NWARP 32
#define NF4 (PLANE/4)             // 676
#define MAXU 2                    // targets per warp (covers T <= 64)
#define MAXT 64

// scaled anchors = ANCHORS / (416/52) = ANCHORS / 8
__constant__ float c_aw[3] = {1.25f, 2.0f, 4.125f};
__constant__ float c_ah[3] = {1.625f, 3.75f, 2.875f};

// ---------------- global accumulators (zero at module load; reset by last block) ----
__device__ double       d_acc[4];     // iou_sum, conf1_sum, conf2_sum, cls_sum
__device__ int          d_npos;
__device__ unsigned int d_count;

__device__ __forceinline__ float warp_sum(float v) {
#pragma unroll
    for (int o = 16; o > 0; o >>= 1) v += __shfl_down_sync(0xffffffffu, v, o);
    return v;
}

__device__ __forceinline__ float fsigmoid(float x) {
    return __fdividef(1.0f, 1.0f + __expf(-x));
}

// L(x) = log(1 + exp(-x)) = -log(sigmoid(x)); input pre-clamped to +-XCLIP
__device__ __forceinline__ float softplus_neg(float xc) {
    return __logf(1.0f + __expf(-xc));
}

__global__ void __launch_bounds__(TPB) k_fused(const float* __restrict__ input,
                                               const float* __restrict__ targets,
                                               float* __restrict__ out,
                                               int B, int T) {
    // block -> (b, a); one full 52x52 plane per block
    int bx = blockIdx.x;
    int b  = bx / NA;
    int a  = bx % NA;

    size_t plane_base = ((size_t)b * 255 + (size_t)a * 85) * PLANE;

    int tid = threadIdx.x;
    int wid = tid >> 5, lid = tid & 31;

    // ---- (1) issue ALL independent global loads first: conf float4 + target rows ----
    float4 cv = make_float4(0.f, 0.f, 0.f, 0.f);
    if (tid < NF4)
        cv = *reinterpret_cast<const float4*>(
            input + plane_base + (size_t)4 * PLANE + 4 * tid);

    float tv[MAXU][5];
#pragma unroll
    for (int u = 0; u < MAXU; u++) {
        int t = wid + u * NWARP;
        if (t < T) {
            const float* tp = targets + ((size_t)b * T + t) * 5;   // warp-broadcast loads
            tv[u][0] = tp[0]; tv[u][1] = tp[1]; tv[u][2] = tp[2];
            tv[u][3] = tp[3]; tv[u][4] = tp[4];
        }
    }

    // ---- tiny smem state (no big tables) ----
    __shared__ unsigned int s_maskbm[NBMW];   // mask bit per cell
    __shared__ unsigned int s_ignbm[NBMW];    // ignore (noobj=0) bit per cell
    __shared__ int          s_tlp[MAXT];      // per-target claimed cell (-1 none)
    __shared__ int          s_tcls[MAXT];     // per-target class id
    __shared__ float        s_part[5][NWARP];
    __shared__ int          s_last;

    if (tid < NBMW) { s_maskbm[tid] = 0u; s_ignbm[tid] = 0u; }
    __syncthreads();     // bitmaps zeroed (targets RT overlapped this)

    // ---- (2) decode in registers, post compact state, issue speculative gather ----
    int   sp_lp[MAXU], sp_t[MAXU];
    float sp_v0[MAXU], sp_v1[MAXU], sp_v2[MAXU];

#pragma unroll
    for (int u = 0; u < MAXU; u++) {
        sp_lp[u] = -1;
        sp_v0[u] = 0.f; sp_v1[u] = 0.f; sp_v2[u] = 0.f;
        int t = wid + u * NWARP;
        if (t >= MAXT) continue;

        int  lp = -1, cls = 0;
        bool claim = false;
        float iou_a = 0.0f;

        if (t < T) {
            float c = tv[u][0], x = tv[u][1], y = tv[u][2], w = tv[u][3], h = tv[u][4];
            bool ok = (c + x + y + w + h != 0.0f);      // valid = sum != 0

            float gx = x * GW, gy = y * GH, gw = w * GW, gh = h * GH;
            int gi = (int)gx, gj = (int)gy;
            ok = ok && gi >= 0 && gi < GW && gj >= 0 && gj < GH;

            if (ok) {
                int cell = gj * GW + gi;
                float area = gw * gh;
                float ious[3];
                float best_iou = -1.0f;
                int best = 0;
#pragma unroll
                for (int k = 0; k < 3; k++) {
                    float inter = fminf(gw, c_aw[k]) * fminf(gh, c_ah[k]);
                    float iou = inter / (area + c_aw[k] * c_ah[k] - inter + 1e-16f);
                    ious[k] = iou;
                    if (iou > best_iou) { best_iou = iou; best = k; } // argmax (first)
                }
                iou_a = ious[a];
                cls   = (int)c;
                if (best == a) { claim = true; lp = cell; }
                if (lid == 0 && iou_a > 0.5f)
                    atomicOr(&s_ignbm[cell >> 5], 1u << (cell & 31));
            }
        }

        if (lid == 0) {
            s_tlp[t]  = claim ? lp : -1;    // unconditional write: no init needed
            s_tcls[t] = cls;
            if (claim) atomicOr(&s_maskbm[lp >> 5], 1u << (lp & 31));
        }

        if (claim) {
            sp_lp[u] = lp;
            sp_t[u]  = t;
            // speculative 85-channel gather, in flight across the barrier
            size_t base = plane_base + lp;
            sp_v0[u] = input[base + (size_t)lid * PLANE];
            sp_v1[u] = input[base + (size_t)(lid + 32) * PLANE];
            sp_v2[u] = (lid < 21) ? input[base + (size_t)(lid + 64) * PLANE] : 0.0f;
        }
    }
    __syncthreads();

    float a_iou = 0.f, a_c1 = 0.f, a_c2 = 0.f, a_cl = 0.f, a_np = 0.f;

    // ---- (3) dense conf consume from bitmaps (softplus: both bce terms) ----
    if (tid < NF4) {
        float cl[4] = {cv.x, cv.y, cv.z, cv.w};
#pragma unroll
        for (int k = 0; k < 4; k++) {
            int lp = 4 * tid + k;
            float xc = fminf(fmaxf(cl[k], -XCLIP), XCLIP);
            float L  = softplus_neg(xc);            // = -log(clip(sigmoid))
            bool m   = (s_maskbm[lp >> 5] >> (lp & 31)) & 1u;
            bool ign = (s_ignbm[lp >> 5]  >> (lp & 31)) & 1u;
            a_c1 += m      ? L        : LOG1MEPS;   // bce(conf*mask, mask)
            a_c2 += (!ign) ? (L + xc) : LOG1MEPS;   // bce(conf*noobj, 0)
        }
    }

    // ---- (4) claiming warps: winner scan (last-wins) + class union + accumulate ----
#pragma unroll
    for (int u = 0; u < MAXU; u++) {
        int lp = sp_lp[u];
        if (lp < 0) continue;

        int maxt = -1;
        unsigned w0 = 0u, w1 = 0u, w2 = 0u;
        for (int tt = 0; tt < T; tt++) {            // uniform broadcast LDS scan
            if (s_tlp[tt] == lp) {
                maxt = tt;                          // ascending -> ends at max
                int cc = s_tcls[tt];
                if (cc >= 0 && cc < 32)       w0 |= 1u << cc;
                else if (cc >= 32 && cc < 64) w1 |= 1u << (cc - 32);
                else if (cc >= 64 && cc < NCLS) w2 |= 1u << (cc - 64);
            }
        }
        if (maxt != sp_t[u]) continue;              // another target won this cell

        float v0 = sp_v0[u], v1 = sp_v1[u], v2 = sp_v2[u];
        int j = lp / GW;
        int i = lp - j * GW;

        float xl = __shfl_sync(0xffffffffu, v0, 0);
        float yl = __shfl_sync(0xffffffffu, v0, 1);
        float wl = __shfl_sync(0xffffffffu, v0, 2);
        float hl = __shfl_sync(0xffffffffu, v0, 3);

        float kx = tv[u][1] * GW, ky = tv[u][2] * GH;
        float kw = tv[u][3] * GW, kh = tv[u][4] * GH;

        float hx = fsigmoid(xl) + (float)i;
        float hy = fsigmoid(yl) + (float)j;
        float hw = __expf(wl) * c_aw[a];
        float hh = __expf(hl) * c_ah[a];

        float iw = fminf(hx + hw * 0.5f, kx + kw * 0.5f) -
                   fmaxf(hx - hw * 0.5f, kx - kw * 0.5f);
        iw = fmaxf(iw, 0.0f);
        float ih = fminf(hy + hh * 0.5f, ky + kh * 0.5f) -
                   fmaxf(hy - hh * 0.5f, ky - kh * 0.5f);
        ih = fmaxf(ih, 0.0f);
        float inter = iw * ih;
        float iou = inter / (hw * hh + kw * kh - inter + 1e-16f);
        if (lid == 0) { a_iou += 1.0f - iou; a_np += 1.0f; }

        // class bce via softplus: t ? L(v) : L(v)+v
        float cls_sum = 0.0f;
        if (lid >= 5) {
            int c = lid - 5;                       // classes 0..26 from v0
            float vc = fminf(fmaxf(v0, -XCLIP), XCLIP);
            float L  = softplus_neg(vc);
            bool tt = (w0 >> c) & 1u;
            cls_sum += tt ? L : (L + vc);
        }
        {
            int c = lid + 27;                      // classes 27..58 from v1
            float vc = fminf(fmaxf(v1, -XCLIP), XCLIP);
            float L  = softplus_neg(vc);
            unsigned word = (c < 32) ? w0 : (c < 64 ? w1 : w2);
            bool tt = (word >> (c & 31)) & 1u;
            cls_sum += tt ? L : (L + vc);
        }
        if (lid < 21) {
            int c = lid + 59;                      // classes 59..79 from v2
            float vc = fminf(fmaxf(v2, -XCLIP), XCLIP);
            float L  = softplus_neg(vc);
            bool tt = (w2 >> (c & 31)) & 1u;
            cls_sum += tt ? L : (L + vc);
        }
        a_cl += cls_sum;
    }

    // ---- block reduction (32 warps) ----
    a_iou = warp_sum(a_iou);
    a_c1  = warp_sum(a_c1);
    a_c2  = warp_sum(a_c2);
    a_cl  = warp_sum(a_cl);
    a_np  = warp_sum(a_np);

    if (lid == 0) {
        s_part[0][wid] = a_iou; s_part[1][wid] = a_c1; s_part[2][wid] = a_c2;
        s_part[3][wid] = a_cl;  s_part[4][wid] = a_np;
    }
    __syncthreads();
    if (wid == 0) {
        float v0 = s_part[0][lid];
        float v1 = s_part[1][lid];
        float v2 = s_part[2][lid];
        float v3 = s_part[3][lid];
        float v4 = s_part[4][lid];
        v0 = warp_sum(v0); v1 = warp_sum(v1); v2 = warp_sum(v2);
        v3 = warp_sum(v3); v4 = warp_sum(v4);
        if (lid == 0) {
            if (v0 != 0.f) atomicAdd(&d_acc[0], (double)v0);
            atomicAdd(&d_acc[1], (double)v1);
            atomicAdd(&d_acc[2], (double)v2);
            if (v3 != 0.f) atomicAdd(&d_acc[3], (double)v3);
            if (v4 != 0.f) atomicAdd(&d_npos, (int)(v4 + 0.5f));
        }
    }

    // ---- last-block finalize + reset (graph-replay safe) ----
    __threadfence();
    if (tid == 0) {
        unsigned prev = atomicAdd(&d_count, 1u);
        s_last = (prev == gridDim.x - 1) ? 1 : 0;
    }
    __syncthreads();
    if (s_last && tid == 0) {
        double iou = d_acc[0], c1 = d_acc[1], c2 = d_acc[2], cls = d_acc[3];
        int np = d_npos;
        double N = (double)B * NA * GH * GW;
        float loss_iou  = (float)iou;
        float loss_conf = (float)(c1 / N + 0.5 * (c2 / N));
        double npf = (np < 1) ? 1.0 : (double)np;
        float loss_cls  = (float)(cls / (npf * (double)NCLS));
        out[0] = 0.5f * loss_iou + loss_conf + loss_cls;
        out[1] = loss_iou;
        out[2] = loss_conf;
        out[3] = loss_cls;
        d_acc[0] = 0.0; d_acc[1] = 0.0; d_acc[2] = 0.0; d_acc[3] = 0.0;
        d_npos = 0;
        d_count = 0u;
    }
}

extern "C" void kernel_launch(void* const* d_in, const int* in_sizes, int n_in,
                              void* d_out, int out_size) {
    const float* input   = (const float*)d_in[0];
    const float* targets = (const float*)d_in[1];

    int B = in_sizes[0] / (255 * GH * GW);
    int T = in_sizes[1] / (B * 5);

    int nblk = B * NA;   // 96 blocks, one wave
    k_fused<<<nblk, TPB>>>(input, targets, (float*)d_out, B, T);
}

// round 11
// speedup vs baseline: 1.3208x; 1.3208x over previous
#include <cuda_runtime.h>

// ---------------- problem constants ----------------
#define NA 3
#define GH 52
#define GW 52
#define NCLS 80
#define PLANE (GH*GW)             // 2704
#define EPSF 1e-7f
#define LOG1MEPS 1.00000011686097e-07f   // -log(1 - 1e-7)
#define XCLIP 16.118095f          // log((1-EPS)/EPS)
#define TPB 1024
#define NWARP 32
#define NF4 (PLANE/4)             // 676
#define MAXU 2                    // targets per warp (covers T <= 64)

// scaled anchors = ANCHORS / (416/52) = ANCHORS / 8
__constant__ float c_aw[3] = {1.25f, 2.0f, 4.125f};
__constant__ float c_ah[3] = {1.625f, 3.75f, 2.875f};

// ---------------- global accumulators (zero at module load; reset by last block) ----
__device__ double       d_acc[4];     // iou_sum, conf1_sum, conf2_sum, cls_sum
__device__ int          d_npos;
__device__ unsigned int d_count;

__device__ __forceinline__ float warp_sum(float v) {
#pragma unroll
    for (int o = 16; o > 0; o >>= 1) v += __shfl_down_sync(0xffffffffu, v, o);
    return v;
}

__device__ __forceinline__ float fsigmoid(float x) {
    return __fdividef(1.0f, 1.0f + __expf(-x));
}

// L(x) = log(1 + exp(-x)) = -log(sigmoid(x)); input pre-clamped to +-XCLIP
__device__ __forceinline__ float softplus_neg(float xc) {
    return __logf(1.0f + __expf(-xc));
}

__global__ void __launch_bounds__(TPB) k_fused(const float* __restrict__ input,
                                               const float* __restrict__ targets,
                                               float* __restrict__ out,
                                               int B, int T) {
    // block -> (b, a); one full 52x52 plane per block
    int bx = blockIdx.x;
    int b  = bx / NA;
    int a  = bx % NA;

    size_t plane_base = ((size_t)b * 255 + (size_t)a * 85) * PLANE;

    int tid = threadIdx.x;
    int wid = tid >> 5, lid = tid & 31;

    // ---- issue conf float4 load FIRST (independent of everything below) ----
    float4 cv = make_float4(0.f, 0.f, 0.f, 0.f);
    if (tid < NF4)
        cv = *reinterpret_cast<const float4*>(
            input + plane_base + (size_t)4 * PLANE + 4 * tid);

    __shared__ int           s_win[PLANE];        // winner target idx, -1 none
    __shared__ unsigned int  s_cls[PLANE * 3];    // 80-bit class union
    __shared__ unsigned char s_ign[PLANE];        // 1 => noobj = 0
    __shared__ float         s_part[5][NWARP];

    for (int k = tid; k < PLANE; k += TPB) { s_win[k] = -1; s_ign[k] = 0; }
    for (int k = tid; k < 3 * PLANE; k += TPB) s_cls[k] = 0u;
    __syncthreads();

    // ---- warp-per-target decode + SPECULATIVE channel gather (no barrier between) ----
    int   sp_lp[MAXU], sp_t[MAXU];
    float sp_v0[MAXU], sp_v1[MAXU], sp_v2[MAXU];

#pragma unroll
    for (int u = 0; u < MAXU; u++) {
        sp_lp[u] = -1;
        sp_v0[u] = 0.f; sp_v1[u] = 0.f; sp_v2[u] = 0.f;
        int t = wid + u * NWARP;
        if (t < T) {
            const float* tp = targets + ((size_t)b * T + t) * 5;
            float c = tp[0], x = tp[1], y = tp[2], w = tp[3], h = tp[4];
            bool ok = (c + x + y + w + h != 0.0f);       // valid = sum != 0

            float gx = x * GW, gy = y * GH, gw = w * GW, gh = h * GH;
            int gi = (int)gx, gj = (int)gy;
            ok = ok && gi >= 0 && gi < GW && gj >= 0 && gj < GH;

            if (ok) {
                int lp = gj * GW + gi;
                float area = gw * gh;
                float ious[3];
                float best_iou = -1.0f;
                int best = 0;
#pragma unroll
                for (int k = 0; k < 3; k++) {
                    float inter = fminf(gw, c_aw[k]) * fminf(gh, c_ah[k]);
                    float iou = inter / (area + c_aw[k] * c_ah[k] - inter + 1e-16f);
                    ious[k] = iou;
                    if (iou > best_iou) { best_iou = iou; best = k; } // argmax (first)
                }

                if (lid == 0 && ious[a] > 0.5f) s_ign[lp] = 1;   // benign races
                if (best == a) {
                    if (lid == 0) {
                        atomicMax(&s_win[lp], t);                // last-update-wins
                        int cls = (int)c;
                        if (cls >= 0 && cls < NCLS)
                            atomicOr(&s_cls[lp + ((cls >> 5) * PLANE)],
                                     1u << (cls & 31));
                    }
                    sp_lp[u] = lp;
                    sp_t[u]  = t;
                    // speculative gather: lanes cover the 85 channels, in flight
                    // across the barrier below
                    size_t base = plane_base + lp;
                    sp_v0[u] = input[base + (size_t)lid * PLANE];
                    sp_v1[u] = input[base + (size_t)(lid + 32) * PLANE];
                    sp_v2[u] = (lid < 21) ? input[base + (size_t)(lid + 64) * PLANE]
                                          : 0.0f;
                }
            }
        }
    }
    __syncthreads();

    float a_iou = 0.f, a_c1 = 0.f, a_c2 = 0.f, a_cl = 0.f, a_np = 0.f;

    // ---- dense conf consume (softplus: both bce terms from one EX2+LG2) ----
    if (tid < NF4) {
        float cl[4] = {cv.x, cv.y, cv.z, cv.w};
#pragma unroll
        for (int k = 0; k < 4; k++) {
            int lp = 4 * tid + k;
            float xc = fminf(fmaxf(cl[k], -XCLIP), XCLIP);
            float L  = softplus_neg(xc);            // = -log(clip(sigmoid))
            bool m   = (s_win[lp] >= 0);
            bool ign = (s_ign[lp] != 0);
            a_c1 += m      ? L        : LOG1MEPS;   // bce(conf*mask, mask)
            a_c2 += (!ign) ? (L + xc) : LOG1MEPS;   // bce(conf*noobj, 0)
        }
    }

    // ---- winner warps accumulate their speculatively-gathered cell ----
#pragma unroll
    for (int u = 0; u < MAXU; u++) {
        int lp = sp_lp[u];
        if (lp >= 0 && s_win[lp] == sp_t[u]) {       // this warp's target won the cell
            float v0 = sp_v0[u], v1 = sp_v1[u], v2 = sp_v2[u];
            int j = lp / GW;
            int i = lp - j * GW;

            float xl = __shfl_sync(0xffffffffu, v0, 0);
            float yl = __shfl_sync(0xffffffffu, v0, 1);
            float wl = __shfl_sync(0xffffffffu, v0, 2);
            float hl = __shfl_sync(0xffffffffu, v0, 3);

            // re-read own target's box (L1/L2-hot)
            const float* tp = targets + ((size_t)b * T + sp_t[u]) * 5;
            float kx = tp[1] * GW, ky = tp[2] * GH;
            float kw = tp[3] * GW, kh = tp[4] * GH;

            float hx = fsigmoid(xl) + (float)i;
            float hy = fsigmoid(yl) + (float)j;
            float hw = __expf(wl) * c_aw[a];
            float hh = __expf(hl) * c_ah[a];

            float iw = fminf(hx + hw * 0.5f, kx + kw * 0.5f) -
                       fmaxf(hx - hw * 0.5f, kx - kw * 0.5f);
            iw = fmaxf(iw, 0.0f);
            float ih = fminf(hy + hh * 0.5f, ky + kh * 0.5f) -
                       fmaxf(hy - hh * 0.5f, ky - kh * 0.5f);
            ih = fmaxf(ih, 0.0f);
            float inter = iw * ih;
            float iou = inter / (hw * hh + kw * kh - inter + 1e-16f);
            if (lid == 0) { a_iou += 1.0f - iou; a_np += 1.0f; }

            unsigned w0 = s_cls[lp];
            unsigned w1 = s_cls[lp + PLANE];
            unsigned w2 = s_cls[lp + 2 * PLANE];

            // class bce via softplus: t ? L(v) : L(v)+v
            float cls_sum = 0.0f;
            if (lid >= 5) {
                int c = lid - 5;                       // classes 0..26 from v0
                float vc = fminf(fmaxf(v0, -XCLIP), XCLIP);
                float L  = softplus_neg(vc);
                bool tt = (w0 >> c) & 1u;
                cls_sum += tt ? L : (L + vc);
            }
            {
                int c = lid + 27;                      // classes 27..58 from v1
                float vc = fminf(fmaxf(v1, -XCLIP), XCLIP);
                float L  = softplus_neg(vc);
                unsigned word = (c < 32) ? w0 : (c < 64 ? w1 : w2);
                bool tt = (word >> (c & 31)) & 1u;
                cls_sum += tt ? L : (L + vc);
            }
            if (lid < 21) {
                int c = lid + 59;                      // classes 59..79 from v2
                float vc = fminf(fmaxf(v2, -XCLIP), XCLIP);
                float L  = softplus_neg(vc);
                bool tt = (w2 >> (c & 31)) & 1u;
                cls_sum += tt ? L : (L + vc);
            }
            a_cl += cls_sum;
        }
    }

    // ---- block reduction (32 warps) ----
    a_iou = warp_sum(a_iou);
    a_c1  = warp_sum(a_c1);
    a_c2  = warp_sum(a_c2);
    a_cl  = warp_sum(a_cl);
    a_np  = warp_sum(a_np);

    if (lid == 0) {
        s_part[0][wid] = a_iou; s_part[1][wid] = a_c1; s_part[2][wid] = a_c2;
        s_part[3][wid] = a_cl;  s_part[4][wid] = a_np;
    }
    __syncthreads();
    if (wid == 0) {
        float v0 = s_part[0][lid];
        float v1 = s_part[1][lid];
        float v2 = s_part[2][lid];
        float v3 = s_part[3][lid];
        float v4 = s_part[4][lid];
        v0 = warp_sum(v0); v1 = warp_sum(v1); v2 = warp_sum(v2);
        v3 = warp_sum(v3); v4 = warp_sum(v4);
        if (lid == 0) {
            if (v0 != 0.f) atomicAdd(&d_acc[0], (double)v0);
            atomicAdd(&d_acc[1], (double)v1);
            atomicAdd(&d_acc[2], (double)v2);
            if (v3 != 0.f) atomicAdd(&d_acc[3], (double)v3);
            if (v4 != 0.f) atomicAdd(&d_npos, (int)(v4 + 0.5f));

            // ---- tail: fence + last-block finalize, all on thread 0 only ----
            __threadfence();
            unsigned prev = atomicAdd(&d_count, 1u);
            if (prev == gridDim.x - 1) {
                double iou = d_acc[0], c1 = d_acc[1], c2 = d_acc[2], cls = d_acc[3];
                int np = d_npos;
                double N = (double)B * NA * GH * GW;
                float loss_iou  = (float)iou;
                float loss_conf = (float)(c1 / N + 0.5 * (c2 / N));
                double npf = (np < 1) ? 1.0 : (double)np;
                float loss_cls  = (float)(cls / (npf * (double)NCLS));
                out[0] = 0.5f * loss_iou + loss_conf + loss_cls;
                out[1] = loss_iou;
                out[2] = loss_conf;
                out[3] = loss_cls;
                // reset for next graph replay
                d_acc[0] = 0.0; d_acc[1] = 0.0; d_acc[2] = 0.0; d_acc[3] = 0.0;
                d_npos = 0;
                d_count = 0u;
            }
        }
    }
}

extern "C" void kernel_launch(void* const* d_in, const int* in_sizes, int n_in,
                              void* d_out, int out_size) {
    const float* input   = (const float*)d_in[0];
    const float* targets = (const float*)d_in[1];

    int B = in_sizes[0] / (255 * GH * GW);
    int T = in_sizes[1] / (B * 5);

    int nblk = B * NA;   // 96 blocks, one wave
    k_fused<<<nblk, TPB>>>(input, targets, (float*)d_out, B, T);
}